// round 8
// baseline (speedup 1.0000x reference)
#include <cuda_runtime.h>
#include <cstdint>

#define SEQ    512
#define BATCH  256
#define NIN    32
#define HID    128
#define NOUT   16
#define FEAT   9          // silu + 8 spline basis
#define K1X    (NIN * FEAT)   // 288
#define K1H    (HID * FEAT)   // 1152
#define KSPLIT 16
#define NBLK   128
#define XC_ROWS 32

// ---------------- scratch (device globals; no allocation allowed) ----------
__device__ float g_XC[SEQ * BATCH * HID];          // [t][b][o] x-part contribution
__device__ float g_P[2][KSPLIT * BATCH * HID];     // [parity][ks][b][o] partials
__device__ float g_W1x[K1X * HID];                 // fused layer1 x-part weights
__device__ float g_W1h[K1H * HID];                 // fused layer1 h-part weights
__device__ float g_W2[K1H * NOUT];                 // fused layer2 weights
__device__ unsigned int g_bar_count;
__device__ volatile unsigned int g_bar_gen;

// ---------------- KAN feature expansion (matches reference Cox-de Boor) ----
// grid: knots t_j = -4 + 1.6*(j-3), j=0..11  (K=3, G=5, range [-4,4])
__device__ __forceinline__ void kan_feats(float x, float* f) {
    float sig = 1.0f / (1.0f + __expf(-x));
    f[0] = x * sig;                                   // silu base
    float B[11];
#pragma unroll
    for (int j = 0; j < 11; j++) {
        float tj  = -4.0f + 1.6f * (float)(j - 3);
        float tj1 = -4.0f + 1.6f * (float)(j - 2);
        B[j] = (x >= tj && x < tj1) ? 1.0f : 0.0f;
    }
#pragma unroll
    for (int d = 1; d <= 3; d++) {
        float inv = 1.0f / (1.6f * (float)d);
#pragma unroll
        for (int j = 0; j < 11 - d; j++) {
            float tj   = -4.0f + 1.6f * (float)(j - 3);
            float tjd1 = -4.0f + 1.6f * (float)(j + d - 2);
            B[j] = ((x - tj) * B[j] + (tjd1 - x) * B[j + 1]) * inv;
        }
    }
#pragma unroll
    for (int k = 0; k < 8; k++) f[1 + k] = B[k];
}

// ---------------- weight fusion -------------------------------------------
// W[(i*9+0), o] = sb[i,o];  W[(i*9+1+k), o] = coef[i,o,k] * sp[i,o]
__global__ void prep_kernel(const float* __restrict__ coef1, const float* __restrict__ sb1,
                            const float* __restrict__ sp1,   const float* __restrict__ coef2,
                            const float* __restrict__ sb2,   const float* __restrict__ sp2) {
    int idx = blockIdx.x * blockDim.x + threadIdx.x;
    if (idx < (K1X + K1H) * HID) {
        int j = idx >> 7;        // 0..1439
        int o = idx & 127;
        int i = j / FEAT;        // 0..159
        int m = j % FEAT;
        float w = (m == 0) ? sb1[i * HID + o]
                           : coef1[(i * HID + o) * 8 + (m - 1)] * sp1[i * HID + o];
        if (i < NIN) g_W1x[j * HID + o] = w;
        else         g_W1h[(j - K1X) * HID + o] = w;
    }
    if (idx < K1H * NOUT) {
        int j = idx >> 4;
        int o = idx & 15;
        int i = j / FEAT;
        int m = j % FEAT;
        float w = (m == 0) ? sb2[i * NOUT + o]
                           : coef2[(i * NOUT + o) * 8 + (m - 1)] * sp2[i * NOUT + o];
        g_W2[j * NOUT + o] = w;
    }
}

// ---------------- XC precompute: x-part of layer1 for all timesteps --------
// row id rid = t*256 + b;   XC[rid][o] = sum_j feats_x[rid][j] * W1x[j][o]
__global__ __launch_bounds__(256) void xc_kernel(const float* __restrict__ x) {
    __shared__ float fs[XC_ROWS * 289];   // 289 = 288 + pad
    int row0 = blockIdx.x * XC_ROWS;
    int tid = threadIdx.x;
#pragma unroll
    for (int q = 0; q < 4; q++) {
        int e = tid + q * 256;            // 1024 (row,input) evals
        int r = e >> 5, i = e & 31;
        int rid = row0 + r;
        int t = rid >> 8, b = rid & 255;
        float xv = x[(b * SEQ + t) * NIN + i];
        float f[FEAT];
        kan_feats(xv, f);
#pragma unroll
        for (int m = 0; m < FEAT; m++) fs[r * 289 + i * FEAT + m] = f[m];
    }
    __syncthreads();
    int tx = tid & 31, ty = tid >> 5;     // 32 col-groups x 8 row-groups
    float acc[16];
#pragma unroll
    for (int u = 0; u < 16; u++) acc[u] = 0.0f;
#pragma unroll 4
    for (int k = 0; k < K1X; k++) {
        float a0 = fs[(ty * 4 + 0) * 289 + k];
        float a1 = fs[(ty * 4 + 1) * 289 + k];
        float a2 = fs[(ty * 4 + 2) * 289 + k];
        float a3 = fs[(ty * 4 + 3) * 289 + k];
        float4 bv = *reinterpret_cast<const float4*>(&g_W1x[k * HID + tx * 4]);
        acc[0]  += a0 * bv.x; acc[1]  += a0 * bv.y; acc[2]  += a0 * bv.z; acc[3]  += a0 * bv.w;
        acc[4]  += a1 * bv.x; acc[5]  += a1 * bv.y; acc[6]  += a1 * bv.z; acc[7]  += a1 * bv.w;
        acc[8]  += a2 * bv.x; acc[9]  += a2 * bv.y; acc[10] += a2 * bv.z; acc[11] += a2 * bv.w;
        acc[12] += a3 * bv.x; acc[13] += a3 * bv.y; acc[14] += a3 * bv.z; acc[15] += a3 * bv.w;
    }
#pragma unroll
    for (int q = 0; q < 4; q++) {
        int rid = row0 + ty * 4 + q;
        float4 v = make_float4(acc[q * 4 + 0], acc[q * 4 + 1], acc[q * 4 + 2], acc[q * 4 + 3]);
        *reinterpret_cast<float4*>(&g_XC[rid * HID + tx * 4]) = v;
    }
}

// ---------------- custom grid barrier (128 co-resident blocks) -------------
// __threadfence (gpu scope) flushes L1D on sm_103a -> cross-SM data visible.
__device__ __forceinline__ void grid_barrier() {
    __threadfence();            // release this block's P stores
    __syncthreads();
    if (threadIdx.x == 0) {
        unsigned int gen = g_bar_gen;
        unsigned int arrived = atomicAdd(&g_bar_count, 1u);
        if (arrived == NBLK - 1) {
            atomicExch(&g_bar_count, 0u);
            __threadfence();
            g_bar_gen = gen + 1u;
        } else {
            while (g_bar_gen == gen) { __nanosleep(64); }
        }
    }
    __syncthreads();
    __threadfence();            // acquire: invalidate L1 before reading peers' P
}

// ---------------- persistent recurrent kernel ------------------------------
// 128 blocks = 4 M-tiles(64 rows) x 2 N-tiles(64 cols) x 16 K-tiles(8 inputs).
// Per step: rebuild A-tile (features of h_{t-1}) in smem, 64x64x72 FFMA GEMM
// against resident W1h tile, store partial P; one grid barrier per step.
__global__ __launch_bounds__(256, 1) void rec_kernel() {
    __shared__ float As[64 * 73];        // padded stride 73 (conflict-free)
    __shared__ float Bs[72 * 64];        // W1h tile, loaded once
    int bid = blockIdx.x;
    int ks = bid & 15;
    int ni = (bid >> 4) & 1;
    int mi = bid >> 5;
    int b0 = mi * 64, o0 = ni * 64, i0 = ks * 8, j0 = ks * 72;
    int tid = threadIdx.x;
    for (int idx = tid; idx < 72 * 64; idx += 256)
        Bs[idx] = g_W1h[(j0 + (idx >> 6)) * HID + o0 + (idx & 63)];
    int tx = tid & 15, ty = tid >> 4;

    for (int t = 0; t < SEQ; t++) {
        // ---- phase A: features of h_{t-1} for (my 64 rows) x (my 8 inputs)
        const float* __restrict__ Pold = g_P[(t + 1) & 1];
        const float* __restrict__ xcp  = g_XC + (size_t)(t - 1) * BATCH * HID;
#pragma unroll
        for (int q = 0; q < 2; q++) {
            int e = tid + q * 256;       // 512 evals
            int r = e >> 3, il = e & 7;
            int b = b0 + r, i = i0 + il;
            float hv = 0.0f;
            if (t > 0) {
                hv = xcp[b * HID + i];
#pragma unroll
                for (int s = 0; s < KSPLIT; s++) hv += Pold[(s * BATCH + b) * HID + i];
            }
            float f[FEAT];
            kan_feats(hv, f);
#pragma unroll
            for (int m = 0; m < FEAT; m++) As[r * 73 + il * FEAT + m] = f[m];
        }
        __syncthreads();

        // ---- phase B: 64x64x72 GEMM, 4x4 register tile per thread
        float acc[16];
#pragma unroll
        for (int u = 0; u < 16; u++) acc[u] = 0.0f;
#pragma unroll 4
        for (int k = 0; k < 72; k++) {
            float a0 = As[(ty * 4 + 0) * 73 + k];
            float a1 = As[(ty * 4 + 1) * 73 + k];
            float a2 = As[(ty * 4 + 2) * 73 + k];
            float a3 = As[(ty * 4 + 3) * 73 + k];
            float4 bv = *reinterpret_cast<const float4*>(&Bs[k * 64 + tx * 4]);
            acc[0]  += a0 * bv.x; acc[1]  += a0 * bv.y; acc[2]  += a0 * bv.z; acc[3]  += a0 * bv.w;
            acc[4]  += a1 * bv.x; acc[5]  += a1 * bv.y; acc[6]  += a1 * bv.z; acc[7]  += a1 * bv.w;
            acc[8]  += a2 * bv.x; acc[9]  += a2 * bv.y; acc[10] += a2 * bv.z; acc[11] += a2 * bv.w;
            acc[12] += a3 * bv.x; acc[13] += a3 * bv.y; acc[14] += a3 * bv.z; acc[15] += a3 * bv.w;
        }
        float* __restrict__ Pnew = g_P[t & 1];
#pragma unroll
        for (int q = 0; q < 4; q++) {
            int b = b0 + ty * 4 + q;
            float4 v = make_float4(acc[q * 4 + 0], acc[q * 4 + 1], acc[q * 4 + 2], acc[q * 4 + 3]);
            *reinterpret_cast<float4*>(&Pnew[(ks * BATCH + b) * HID + o0 + tx * 4]) = v;
        }
        grid_barrier();
    }
}

// ---------------- layer 2 on final hidden state ----------------------------
__global__ __launch_bounds__(128) void out_kernel(float* __restrict__ out) {
    __shared__ float fs[K1H];
    int b = blockIdx.x;
    int tid = threadIdx.x;                       // tid == input index i
    float hv = g_XC[((SEQ - 1) * BATCH + b) * HID + tid];
    const float* __restrict__ P = g_P[(SEQ - 1) & 1];
#pragma unroll
    for (int s = 0; s < KSPLIT; s++) hv += P[(s * BATCH + b) * HID + tid];
    float f[FEAT];
    kan_feats(hv, f);
#pragma unroll
    for (int m = 0; m < FEAT; m++) fs[tid * FEAT + m] = f[m];
    __syncthreads();
    int o = tid >> 3, part = tid & 7;            // 16 outputs x 8-way split
    float sum = 0.0f;
    for (int j = part; j < K1H; j += 8) sum += fs[j] * g_W2[j * NOUT + o];
    sum += __shfl_down_sync(0xffffffffu, sum, 4, 8);
    sum += __shfl_down_sync(0xffffffffu, sum, 2, 8);
    sum += __shfl_down_sync(0xffffffffu, sum, 1, 8);
    if (part == 0) out[b * NOUT + o] = sum;
}

// ---------------- launch ----------------------------------------------------
extern "C" void kernel_launch(void* const* d_in, const int* in_sizes, int n_in,
                              void* d_out, int out_size) {
    const float* x     = (const float*)d_in[0];
    const float* coef1 = (const float*)d_in[1];
    const float* sb1   = (const float*)d_in[2];
    const float* sp1   = (const float*)d_in[3];
    const float* coef2 = (const float*)d_in[4];
    const float* sb2   = (const float*)d_in[5];
    const float* sp2   = (const float*)d_in[6];
    float* out = (float*)d_out;

    prep_kernel<<<((K1X + K1H) * HID + 255) / 256, 256>>>(coef1, sb1, sp1, coef2, sb2, sp2);
    xc_kernel<<<(SEQ * BATCH) / XC_ROWS, 256>>>(x);
    rec_kernel<<<NBLK, 256>>>();
    out_kernel<<<BATCH, 128>>>(out);
}

// round 9
// speedup vs baseline: 1.2385x; 1.2385x over previous
#include <cuda_runtime.h>
#include <cstdint>

#define SEQ    512
#define BATCH  256
#define NIN    32
#define HID    128
#define NOUT   16
#define FEAT   9              // silu + 8 spline basis
#define K1X    (NIN * FEAT)   // 288
#define K1H    (HID * FEAT)   // 1152
#define KSPLIT 16
#define NBLK   128
#define XC_ROWS 32
#define AS_STRIDE 68          // 64 rows + pad; %32==4 -> conflict-free feature writes

typedef unsigned long long u64;

// ---------------- scratch (device globals; no allocation allowed) ----------
__device__ float g_XC[SEQ * BATCH * HID];          // [t][b][o] x-part contribution
__device__ float g_P[2][KSPLIT * BATCH * HID];     // [parity][ks][b][o] partials
__device__ float g_W1x[K1X * HID];                 // fused layer1 x-part weights
__device__ float g_W1h[K1H * HID];                 // fused layer1 h-part weights
__device__ float g_W2[K1H * NOUT];                 // fused layer2 weights
__device__ unsigned int g_bar_count;               // monotonic arrivals
__device__ volatile unsigned int g_bar_gen;        // completed step count

// ---------------- packed f32x2 helpers -------------------------------------
__device__ __forceinline__ u64 pack2(float x) {
    u64 r; asm("mov.b64 %0, {%1, %1};" : "=l"(r) : "f"(x)); return r;
}
__device__ __forceinline__ void fma2(u64& d, u64 a, u64 b) {
    asm("fma.rn.f32x2 %0, %1, %2, %0;" : "+l"(d) : "l"(a), "l"(b));
}
__device__ __forceinline__ void unpack2(u64 v, float& lo, float& hi) {
    asm("mov.b64 {%0, %1}, %2;" : "=f"(lo), "=f"(hi) : "l"(v));
}

// ---------------- KAN feature expansion (matches reference Cox-de Boor) ----
__device__ __forceinline__ void kan_feats(float x, float* f) {
    float sig = 1.0f / (1.0f + __expf(-x));
    f[0] = x * sig;                                   // silu base
    float B[11];
#pragma unroll
    for (int j = 0; j < 11; j++) {
        float tj  = -4.0f + 1.6f * (float)(j - 3);
        float tj1 = -4.0f + 1.6f * (float)(j - 2);
        B[j] = (x >= tj && x < tj1) ? 1.0f : 0.0f;
    }
#pragma unroll
    for (int d = 1; d <= 3; d++) {
        float inv = 1.0f / (1.6f * (float)d);
#pragma unroll
        for (int j = 0; j < 11 - d; j++) {
            float tj   = -4.0f + 1.6f * (float)(j - 3);
            float tjd1 = -4.0f + 1.6f * (float)(j + d - 2);
            B[j] = ((x - tj) * B[j] + (tjd1 - x) * B[j + 1]) * inv;
        }
    }
#pragma unroll
    for (int k = 0; k < 8; k++) f[1 + k] = B[k];
}

// ---------------- weight fusion + barrier reset ----------------------------
__global__ void prep_kernel(const float* __restrict__ coef1, const float* __restrict__ sb1,
                            const float* __restrict__ sp1,   const float* __restrict__ coef2,
                            const float* __restrict__ sb2,   const float* __restrict__ sp2) {
    int idx = blockIdx.x * blockDim.x + threadIdx.x;
    if (idx == 0) { g_bar_count = 0u; g_bar_gen = 0u; }   // graph-replay determinism
    if (idx < (K1X + K1H) * HID) {
        int j = idx >> 7;        // 0..1439
        int o = idx & 127;
        int i = j / FEAT;        // 0..159
        int m = j % FEAT;
        float w = (m == 0) ? sb1[i * HID + o]
                           : coef1[(i * HID + o) * 8 + (m - 1)] * sp1[i * HID + o];
        if (i < NIN) g_W1x[j * HID + o] = w;
        else         g_W1h[(j - K1X) * HID + o] = w;
    }
    if (idx < K1H * NOUT) {
        int j = idx >> 4;
        int o = idx & 15;
        int i = j / FEAT;
        int m = j % FEAT;
        float w = (m == 0) ? sb2[i * NOUT + o]
                           : coef2[(i * NOUT + o) * 8 + (m - 1)] * sp2[i * NOUT + o];
        g_W2[j * NOUT + o] = w;
    }
}

// ---------------- XC precompute: x-part of layer1 for all timesteps --------
__global__ __launch_bounds__(256) void xc_kernel(const float* __restrict__ x) {
    __shared__ float fs[XC_ROWS * 289];   // row-major, 289 = 288 + pad
    int row0 = blockIdx.x * XC_ROWS;
    int tid = threadIdx.x;
#pragma unroll
    for (int q = 0; q < 4; q++) {
        int e = tid + q * 256;            // 1024 (row,input) evals
        int r = e >> 5, i = e & 31;
        int rid = row0 + r;
        int t = rid >> 8, b = rid & 255;
        float xv = x[(b * SEQ + t) * NIN + i];
        float f[FEAT];
        kan_feats(xv, f);
#pragma unroll
        for (int m = 0; m < FEAT; m++) fs[r * 289 + i * FEAT + m] = f[m];
    }
    __syncthreads();
    int tx = tid & 31, ty = tid >> 5;     // 32 col-groups x 8 row-groups
    u64 acc[8];
#pragma unroll
    for (int u = 0; u < 8; u++) acc[u] = 0ull;
#pragma unroll 4
    for (int k = 0; k < K1X; k++) {
        u64 a0 = pack2(fs[(ty * 4 + 0) * 289 + k]);
        u64 a1 = pack2(fs[(ty * 4 + 1) * 289 + k]);
        u64 a2 = pack2(fs[(ty * 4 + 2) * 289 + k]);
        u64 a3 = pack2(fs[(ty * 4 + 3) * 289 + k]);
        ulonglong2 bb = *reinterpret_cast<const ulonglong2*>(&g_W1x[k * HID + tx * 4]);
        fma2(acc[0], a0, bb.x); fma2(acc[1], a0, bb.y);
        fma2(acc[2], a1, bb.x); fma2(acc[3], a1, bb.y);
        fma2(acc[4], a2, bb.x); fma2(acc[5], a2, bb.y);
        fma2(acc[6], a3, bb.x); fma2(acc[7], a3, bb.y);
    }
#pragma unroll
    for (int q = 0; q < 4; q++) {
        int rid = row0 + ty * 4 + q;
        float4 v;
        unpack2(acc[2 * q + 0], v.x, v.y);
        unpack2(acc[2 * q + 1], v.z, v.w);
        *reinterpret_cast<float4*>(&g_XC[rid * HID + tx * 4]) = v;
    }
}

// ---------------- grid barrier (128 co-resident blocks) --------------------
// Release: per-thread membar.gl orders P stores to L2 before the L2-serialized
// atomicAdd. Acquire side is free: readers use __ldcg (L2 hit point), so no
// L1-invalidate fence is needed after observing the gen bump.
__device__ __forceinline__ void grid_barrier(unsigned int target) {
    __threadfence();            // release this thread's P stores
    __syncthreads();
    if (threadIdx.x == 0) {
        unsigned int arrived = atomicAdd(&g_bar_count, 1u) + 1u;
        if (arrived == target * NBLK) {
            g_bar_gen = target;                 // volatile store, L2
        } else {
            while (g_bar_gen < target) { __nanosleep(32); }
        }
    }
    __syncthreads();
}

// ---------------- persistent recurrent kernel ------------------------------
// 128 blocks = 4 M-tiles(64 rows) x 2 N-tiles(64 cols) x 16 K-tiles(8 inputs).
__global__ __launch_bounds__(256, 1) void rec_kernel() {
    __shared__ float As[72 * AS_STRIDE];   // k-major: As[k*68 + r]
    __shared__ float Bs[72 * 64];          // W1h tile, resident across steps
    int bid = blockIdx.x;
    int ks = bid & 15;
    int ni = (bid >> 4) & 1;
    int mi = bid >> 5;
    int b0 = mi * 64, o0 = ni * 64, i0 = ks * 8, j0 = ks * 72;
    int tid = threadIdx.x;
    for (int idx = tid; idx < 72 * 64; idx += 256)
        Bs[idx] = g_W1h[(j0 + (idx >> 6)) * HID + o0 + (idx & 63)];
    int tx = tid & 15, ty = tid >> 4;

    for (int t = 0; t < SEQ; t++) {
        // ---- phase A: features of h_{t-1} for (my 64 rows) x (my 8 inputs)
        const float* __restrict__ Pold = g_P[(t + 1) & 1];
        const float* __restrict__ xcp  = g_XC + (size_t)(t - 1) * BATCH * HID;
#pragma unroll
        for (int q = 0; q < 2; q++) {
            int e = tid + q * 256;       // 512 evals
            int r = e >> 3, il = e & 7;
            int b = b0 + r, i = i0 + il;
            float hv = 0.0f;
            if (t > 0) {
                hv = xcp[b * HID + i];
#pragma unroll
                for (int s = 0; s < KSPLIT; s++)
                    hv += __ldcg(&Pold[(s * BATCH + b) * HID + i]);
            }
            float f[FEAT];
            kan_feats(hv, f);
#pragma unroll
            for (int m = 0; m < FEAT; m++)
                As[(il * FEAT + m) * AS_STRIDE + r] = f[m];
        }
        __syncthreads();

        // ---- phase B: 64x64x72 GEMM, 4x4 register tile, packed f32x2 FMA
        u64 acc[8];
#pragma unroll
        for (int u = 0; u < 8; u++) acc[u] = 0ull;
#pragma unroll 4
        for (int k = 0; k < 72; k++) {
            float4 av = *reinterpret_cast<const float4*>(&As[k * AS_STRIDE + ty * 4]);
            ulonglong2 bb = *reinterpret_cast<const ulonglong2*>(&Bs[k * 64 + tx * 4]);
            u64 a0 = pack2(av.x), a1 = pack2(av.y), a2 = pack2(av.z), a3 = pack2(av.w);
            fma2(acc[0], a0, bb.x); fma2(acc[1], a0, bb.y);
            fma2(acc[2], a1, bb.x); fma2(acc[3], a1, bb.y);
            fma2(acc[4], a2, bb.x); fma2(acc[5], a2, bb.y);
            fma2(acc[6], a3, bb.x); fma2(acc[7], a3, bb.y);
        }
        float* __restrict__ Pnew = g_P[t & 1];
#pragma unroll
        for (int q = 0; q < 4; q++) {
            int b = b0 + ty * 4 + q;
            float4 v;
            unpack2(acc[2 * q + 0], v.x, v.y);
            unpack2(acc[2 * q + 1], v.z, v.w);
            *reinterpret_cast<float4*>(&Pnew[(ks * BATCH + b) * HID + o0 + tx * 4]) = v;
        }
        __syncthreads();                  // all stores issued before arrival
        if (t < SEQ - 1) grid_barrier((unsigned int)(t + 1));
    }
}

// ---------------- layer 2 on final hidden state ----------------------------
__global__ __launch_bounds__(128) void out_kernel(float* __restrict__ out) {
    __shared__ float fs[K1H];
    int b = blockIdx.x;
    int tid = threadIdx.x;                       // tid == input index i
    float hv = g_XC[((SEQ - 1) * BATCH + b) * HID + tid];
    const float* __restrict__ P = g_P[(SEQ - 1) & 1];
#pragma unroll
    for (int s = 0; s < KSPLIT; s++) hv += P[(s * BATCH + b) * HID + tid];
    float f[FEAT];
    kan_feats(hv, f);
#pragma unroll
    for (int m = 0; m < FEAT; m++) fs[tid * FEAT + m] = f[m];
    __syncthreads();
    int o = tid >> 3, part = tid & 7;            // 16 outputs x 8-way split
    float sum = 0.0f;
    for (int j = part; j < K1H; j += 8) sum += fs[j] * g_W2[j * NOUT + o];
    sum += __shfl_down_sync(0xffffffffu, sum, 4, 8);
    sum += __shfl_down_sync(0xffffffffu, sum, 2, 8);
    sum += __shfl_down_sync(0xffffffffu, sum, 1, 8);
    if (part == 0) out[b * NOUT + o] = sum;
}

// ---------------- launch ----------------------------------------------------
extern "C" void kernel_launch(void* const* d_in, const int* in_sizes, int n_in,
                              void* d_out, int out_size) {
    const float* x     = (const float*)d_in[0];
    const float* coef1 = (const float*)d_in[1];
    const float* sb1   = (const float*)d_in[2];
    const float* sp1   = (const float*)d_in[3];
    const float* coef2 = (const float*)d_in[4];
    const float* sb2   = (const float*)d_in[5];
    const float* sp2   = (const float*)d_in[6];
    float* out = (float*)d_out;

    prep_kernel<<<((K1X + K1H) * HID + 255) / 256, 256>>>(coef1, sb1, sp1, coef2, sb2, sp2);
    xc_kernel<<<(SEQ * BATCH) / XC_ROWS, 256>>>(x);
    rec_kernel<<<NBLK, 256>>>();
    out_kernel<<<BATCH, 128>>>(out);
}